// round 16
// baseline (speedup 1.0000x reference)
#include <cuda_runtime.h>
#include <cuda_fp16.h>
#include <cstdint>

#define NB 4
#define NN 2048
#define NF 128
#define RT 16        // rows per attention block (M)
#define KT 64        // j per K tile
#define NTILE (NN / KT)
#define SHIFT 4.0f

// ---- scratch (no cudaMalloc allowed) ----
__device__ __half g_WhT_h[NB * NF * NN];   // [b][o][n] fp16
__device__ float  g_f1[NB * NN];
__device__ float  g_f2[NB * NN];

// ---------------------------------------------------------------------------
__device__ __forceinline__ uint32_t smem_u32(const void* p) {
    uint32_t a;
    asm("{ .reg .u64 t; cvta.to.shared.u64 t, %1; cvt.u32.u64 %0, t; }" : "=r"(a) : "l"(p));
    return a;
}
__device__ __forceinline__ uint32_t swz(uint32_t x) { return x ^ ((x >> 3) & 0x70); }

__device__ __forceinline__ uint32_t pkh(float a, float b) {   // fp16x2: lo<-a, hi<-b
    uint32_t r;
    asm("cvt.rn.f16x2.f32 %0, %1, %2;" : "=r"(r) : "f"(b), "f"(a));
    return r;
}
__device__ __forceinline__ void ldm4(uint32_t* r, uint32_t addr) {
    asm volatile("ldmatrix.sync.aligned.m8n8.x4.shared.b16 {%0,%1,%2,%3}, [%4];"
        : "=r"(r[0]), "=r"(r[1]), "=r"(r[2]), "=r"(r[3]) : "r"(addr));
}
__device__ __forceinline__ void mma16816(float* d, const uint32_t* a, const uint32_t* b) {
    asm volatile("mma.sync.aligned.m16n8k16.row.col.f32.f16.f16.f32 "
        "{%0,%1,%2,%3}, {%4,%5,%6,%7}, {%8,%9}, {%0,%1,%2,%3};"
        : "+f"(d[0]), "+f"(d[1]), "+f"(d[2]), "+f"(d[3])
        : "r"(a[0]), "r"(a[1]), "r"(a[2]), "r"(a[3]), "r"(b[0]), "r"(b[1]));
}
#define CPA(dst, src) asm volatile("cp.async.cg.shared.global [%0], [%1], 16;" :: "r"(dst), "l"(src) : "memory")
#define CPC()   asm volatile("cp.async.commit_group;" ::: "memory")
#define CPW(n)  asm volatile("cp.async.wait_group %0;" :: "n"(n) : "memory")

// ---------------------------------------------------------------------------
// Kernel 1 (tensorized): Wh = h@W via 3-term split-fp16 mma.sync.
// Block: 64 rows x 128 o x K=128. 256 threads = 8 warps (4 m x 2 o),
// warp tile 16x64. Outputs: WhT fp16 (transposed), f1, f2.
// ---------------------------------------------------------------------------
#define GA_OFF  0u            // A hi: 2 subs x 8KB; A lo at +16384
#define GB_OFF  32768u        // B hi: 2 subs x 16KB; B lo at +32768 (ends 98304)
#define WF_OFF  98304u        // Wf f32 [128][132] = 67584 (ends 165888)
#define SU_OFF  165888u       // su16 half [128][72] = 18432 (ends 184320)
#define F12_OFF 184320u       // 128 floats (f1 | f2)
#define G1_SMEM (184320 + 512)

__global__ void __launch_bounds__(256, 1)
k_gemm1t(const float* __restrict__ h,
         const float* __restrict__ W,
         const float* __restrict__ a) {
    extern __shared__ char smemA[];
    uint32_t sb = smem_u32(smemA);
    int tid = threadIdx.x;
    int wid = tid >> 5;
    int lane = tid & 31;
    int m0 = blockIdx.x * 64;
    int bb = m0 >> 11;
    int ml = m0 & 2047;

    float* f12 = reinterpret_cast<float*>(smemA + F12_OFF);
    float* Wf  = reinterpret_cast<float*>(smemA + WF_OFF);
    __half* su16 = reinterpret_cast<__half*>(smemA + SU_OFF);

    if (tid < 128) f12[tid] = 0.0f;

    // ---- stage W f32 into smem [128 k][132 pad] (coalesced) ----
    {
        #pragma unroll
        for (int i = 0; i < 16; i++) {
            int w = tid + i * 256;
            int k = w >> 5, c4 = w & 31;
            float4 v = reinterpret_cast<const float4*>(W)[(size_t)k * 32 + c4];
            *reinterpret_cast<float4*>(&Wf[k * 132 + c4 * 4]) = v;
        }
    }

    // ---- convert h rows -> A hi/lo fp16 smem ----
    {
        int r = tid >> 2;
        int cseg = (tid & 3) * 32;
        uint32_t sub = (uint32_t)(cseg >> 6);
        const float4* hp = reinterpret_cast<const float4*>(
            h + (size_t)(m0 + r) * NF + cseg);
        #pragma unroll
        for (int g = 0; g < 4; g++) {
            float4 v0 = hp[g * 2];
            float4 v1 = hp[g * 2 + 1];
            uint32_t h0 = pkh(v0.x, v0.y), h1 = pkh(v0.z, v0.w);
            uint32_t h2 = pkh(v1.x, v1.y), h3 = pkh(v1.z, v1.w);
            float2 f0 = __half22float2(*reinterpret_cast<__half2*>(&h0));
            float2 f1p = __half22float2(*reinterpret_cast<__half2*>(&h1));
            float2 f2p = __half22float2(*reinterpret_cast<__half2*>(&h2));
            float2 f3 = __half22float2(*reinterpret_cast<__half2*>(&h3));
            uint32_t l0 = pkh(v0.x - f0.x, v0.y - f0.y);
            uint32_t l1 = pkh(v0.z - f1p.x, v0.w - f1p.y);
            uint32_t l2 = pkh(v1.x - f2p.x, v1.y - f2p.y);
            uint32_t l3 = pkh(v1.z - f3.x, v1.w - f3.y);
            uint32_t off = sub * 8192u
                         + swz((uint32_t)(r * 128 + ((cseg & 63) + g * 8) * 2));
            *reinterpret_cast<uint4*>(smemA + GA_OFF + off) = make_uint4(h0, h1, h2, h3);
            *reinterpret_cast<uint4*>(smemA + GA_OFF + 16384u + off) = make_uint4(l0, l1, l2, l3);
        }
    }
    __syncthreads();

    // ---- build B (W^T) hi/lo fp16 smem from Wf ----
    {
        int o = tid >> 1;
        int kh = (tid & 1) * 64;
        uint32_t sub = (uint32_t)(tid & 1);
        #pragma unroll
        for (int g = 0; g < 8; g++) {
            int k0 = kh + g * 8;
            float w0 = Wf[(k0 + 0) * 132 + o], w1 = Wf[(k0 + 1) * 132 + o];
            float w2 = Wf[(k0 + 2) * 132 + o], w3 = Wf[(k0 + 3) * 132 + o];
            float w4 = Wf[(k0 + 4) * 132 + o], w5 = Wf[(k0 + 5) * 132 + o];
            float w6 = Wf[(k0 + 6) * 132 + o], w7 = Wf[(k0 + 7) * 132 + o];
            uint32_t h0 = pkh(w0, w1), h1 = pkh(w2, w3);
            uint32_t h2 = pkh(w4, w5), h3 = pkh(w6, w7);
            float2 f0 = __half22float2(*reinterpret_cast<__half2*>(&h0));
            float2 f1p = __half22float2(*reinterpret_cast<__half2*>(&h1));
            float2 f2p = __half22float2(*reinterpret_cast<__half2*>(&h2));
            float2 f3 = __half22float2(*reinterpret_cast<__half2*>(&h3));
            uint32_t l0 = pkh(w0 - f0.x, w1 - f0.y);
            uint32_t l1 = pkh(w2 - f1p.x, w3 - f1p.y);
            uint32_t l2 = pkh(w4 - f2p.x, w5 - f2p.y);
            uint32_t l3 = pkh(w6 - f3.x, w7 - f3.y);
            uint32_t off = sub * 16384u + swz((uint32_t)(o * 128 + g * 16));
            *reinterpret_cast<uint4*>(smemA + GB_OFF + off) = make_uint4(h0, h1, h2, h3);
            *reinterpret_cast<uint4*>(smemA + GB_OFF + 32768u + off) = make_uint4(l0, l1, l2, l3);
        }
    }
    __syncthreads();

    // ---- MMA: warp (wm, wo); 8 ksteps; acc[8][4] ----
    int wm = wid & 3, wo = wid >> 2;
    uint32_t aRowOff = (uint32_t)((wm * 16 + (lane & 7) + ((lane >> 3) & 1) * 8) * 128
                                  + ((lane >> 4) & 1) * 16);
    uint32_t bOff[4];
    #pragma unroll
    for (int nc = 0; nc < 4; nc++) {
        int bRow = wo * 64 + nc * 16 + ((lane >> 4) & 1) * 8 + (lane & 7);
        bOff[nc] = (uint32_t)(bRow * 128) + (uint32_t)(((lane >> 3) & 1) * 16);
    }

    float acc[8][4] = {};
    #pragma unroll
    for (int ks = 0; ks < 8; ks++) {
        uint32_t sub = (uint32_t)(ks >> 2);
        uint32_t ko = 32u * (uint32_t)(ks & 3);
        uint32_t ah[4], al[4], bh[16], bl[16];
        uint32_t aAddr = sb + GA_OFF + sub * 8192u + swz(aRowOff + ko);
        ldm4(ah, aAddr);
        ldm4(al, aAddr + 16384u);
        #pragma unroll
        for (int nc = 0; nc < 4; nc++) {
            uint32_t bAddr = sb + GB_OFF + sub * 16384u + swz(bOff[nc] + ko);
            ldm4(bh + nc * 4, bAddr);
            ldm4(bl + nc * 4, bAddr + 32768u);
        }
        #pragma unroll
        for (int nf = 0; nf < 8; nf++) mma16816(acc[nf], ah, bh + nf * 2);
        #pragma unroll
        for (int nf = 0; nf < 8; nf++) mma16816(acc[nf], ah, bl + nf * 2);
        #pragma unroll
        for (int nf = 0; nf < 8; nf++) mma16816(acc[nf], al, bh + nf * 2);
    }

    // ---- epilogue: f1/f2 partials + transpose buffer ----
    int r0 = wm * 16 + (lane >> 2);
    int r1 = r0 + 8;
    float f1a = 0.f, f1b = 0.f, f2a = 0.f, f2b = 0.f;
    #pragma unroll
    for (int nf = 0; nf < 8; nf++) {
        int c = wo * 64 + nf * 8 + 2 * (lane & 3);
        float a10 = a[c], a11 = a[c + 1];
        float a20 = a[NF + c], a21 = a[NF + c + 1];
        f1a += acc[nf][0] * a10 + acc[nf][1] * a11;
        f1b += acc[nf][2] * a10 + acc[nf][3] * a11;
        f2a += acc[nf][0] * a20 + acc[nf][1] * a21;
        f2b += acc[nf][2] * a20 + acc[nf][3] * a21;
        su16[c * 72 + r0]       = __float2half(acc[nf][0]);
        su16[(c + 1) * 72 + r0] = __float2half(acc[nf][1]);
        su16[c * 72 + r1]       = __float2half(acc[nf][2]);
        su16[(c + 1) * 72 + r1] = __float2half(acc[nf][3]);
    }
    f1a += __shfl_xor_sync(0xffffffffu, f1a, 1);
    f1a += __shfl_xor_sync(0xffffffffu, f1a, 2);
    f1b += __shfl_xor_sync(0xffffffffu, f1b, 1);
    f1b += __shfl_xor_sync(0xffffffffu, f1b, 2);
    f2a += __shfl_xor_sync(0xffffffffu, f2a, 1);
    f2a += __shfl_xor_sync(0xffffffffu, f2a, 2);
    f2b += __shfl_xor_sync(0xffffffffu, f2b, 1);
    f2b += __shfl_xor_sync(0xffffffffu, f2b, 2);
    if ((lane & 3) == 0) {
        atomicAdd(&f12[r0], f1a);
        atomicAdd(&f12[r1], f1b);
        atomicAdd(&f12[64 + r0], f2a);
        atomicAdd(&f12[64 + r1], f2b);
    }
    __syncthreads();

    // ---- global stores ----
    if (tid < 64) g_f1[bb * NN + ml + tid] = f12[tid];
    else if (tid < 128) g_f2[bb * NN + ml + tid - 64] = f12[tid];
    {
        int o = tid >> 1, half = tid & 1;
        const uint4* src = reinterpret_cast<const uint4*>(su16 + o * 72 + half * 32);
        uint4* dst = reinterpret_cast<uint4*>(
            g_WhT_h + (size_t)(bb * 128 + o) * NN + ml + half * 32);
        dst[0] = src[0]; dst[1] = src[1]; dst[2] = src[2]; dst[3] = src[3];
    }
}

// ---------------------------------------------------------------------------
// Kernel 2: fused attention, RT=16, 256 threads, 4 CTAs/SM.
// 8 warps = 2 K-groups x 4 wc; warp tile 16x32, 2 ksteps/warp.
// Single B plane, adj via LDG->registers. K-group partials merged via smem.
// ---------------------------------------------------------------------------
#define AS_OFF  0u            // 2 bufs x 2KB (fp16 P tile 16x64)
#define BT_OFF  4096u         // 2 bufs x 16KB
#define F2_OFF  36864u        // 2048 floats
#define DI_OFF  45056u        // 16 floats
#define SMEM_TOT (45056 + 256)

// phase A for tile tt: adj in registers; P (fp16, 4 j/thread) into bufA[tt&1]
__device__ __forceinline__ float phase_a(int tt, char* smemA, float f1v, int4 m0,
                                         const float* f2p, uint32_t aRel) {
    float4 fa = *reinterpret_cast<const float4*>(f2p);
    float s0 = f1v + fa.x; s0 = fmaxf(s0, 0.2f * s0);
    float s1 = f1v + fa.y; s1 = fmaxf(s1, 0.2f * s1);
    float s2 = f1v + fa.z; s2 = fmaxf(s2, 0.2f * s2);
    float s3 = f1v + fa.w; s3 = fmaxf(s3, 0.2f * s3);
    float p0 = (m0.x > 0) ? __expf(s0 - SHIFT) : 0.0f;
    float p1 = (m0.y > 0) ? __expf(s1 - SHIFT) : 0.0f;
    float p2 = (m0.z > 0) ? __expf(s2 - SHIFT) : 0.0f;
    float p3 = (m0.w > 0) ? __expf(s3 - SHIFT) : 0.0f;
    uint32_t off = AS_OFF + (uint32_t)(tt & 1) * 2048u + aRel;
    *reinterpret_cast<uint2*>(smemA + off) = make_uint2(pkh(p0, p1), pkh(p2, p3));
    return (p0 + p1) + (p2 + p3);
}

__global__ void __launch_bounds__(256, 4)
k_attn(const int* __restrict__ adj, float* __restrict__ out) {
    extern __shared__ char smemA[];
    uint32_t sb = smem_u32(smemA);
    int tid = threadIdx.x;
    int wid = tid >> 5;
    int lane = tid & 31;
    int b = blockIdx.y;
    int row0 = blockIdx.x * RT;

    float* f2s = reinterpret_cast<float*>(smemA + F2_OFF);
    float* di = reinterpret_cast<float*>(smemA + DI_OFF);

    // ---- preload f2 row (8KB, 2 float4 per thread) ----
    {
        const float4* s4 = reinterpret_cast<const float4*>(g_f2 + b * NN);
        float4* d4 = reinterpret_cast<float4*>(f2s);
        d4[tid] = s4[tid];
        d4[tid + 256] = s4[tid + 256];
    }

    // ---- per-thread phase-A constants ----
    int r = tid >> 4;                 // 0..15
    int c4 = (tid & 15) * 4;          // j offset within tile
    float f1v = g_f1[b * NN + row0 + r];
    uint32_t aRel = swz((uint32_t)(r * 128 + (tid & 15) * 8));
    const int* adjp = adj + (size_t)(row0 + r) * NN + c4;

    // ---- MMA fragment addresses: kg = wid>>2, wc = wid&3; warp tile 16x32 ----
    int kg = wid >> 2;
    int wc = wid & 3;
    uint32_t aRowOff = (uint32_t)(((lane & 7) + ((lane >> 3) & 1) * 8) * 128
                                  + ((lane >> 4) & 1) * 16);
    int bRow = wc * 32 + ((lane >> 4) & 1) * 8 + (lane & 7);
    uint32_t bBase = (uint32_t)(bRow * 128) + (uint32_t)(((lane >> 3) & 1) * 16);

    // cp.async B mapping (4 x 16B per thread per tile)
    uint32_t cpDst[4];
    const __half* cpSrcBase[4];
    #pragma unroll
    for (int k = 0; k < 4; k++) {
        int s = tid + k * 256;
        int o = s >> 3, seg = s & 7;
        cpDst[k] = swz((uint32_t)(o * 128 + seg * 16));
        cpSrcBase[k] = g_WhT_h + ((size_t)(b * 128 + o) * NN + seg * 8);
    }

    float acc[4][4] = {};
    float dacc = 0.0f;

    // prologue: B(0); f2 visible; phase A(0) with direct adj load
    {
        uint32_t dbase = sb + BT_OFF;
        #pragma unroll
        for (int k = 0; k < 4; k++) CPA(dbase + cpDst[k], cpSrcBase[k]);
        CPC();
    }
    __syncthreads();
    {
        int4 m0 = *reinterpret_cast<const int4*>(adjp);
        dacc += phase_a(0, smemA, f1v, m0, f2s + c4, aRel);
    }

    for (int t = 0; t < NTILE; t++) {
        uint32_t bufB = sb + BT_OFF + (uint32_t)(t & 1) * 16384u;
        uint32_t bufA = sb + AS_OFF + (uint32_t)(t & 1) * 2048u;

        __syncthreads();   // phaseA(t) + MMA(t-1) complete everywhere

        int4 nm0;
        if (t + 1 < NTILE) {
            uint32_t dbase = sb + BT_OFF + (uint32_t)((t + 1) & 1) * 16384u;
            #pragma unroll
            for (int k = 0; k < 4; k++) CPA(dbase + cpDst[k], cpSrcBase[k] + (t + 1) * KT);
            CPC();
            nm0 = *reinterpret_cast<const int4*>(adjp + (t + 1) * KT);   // hidden under MMA
            CPW(1);        // B(t) landed
        } else {
            CPW(0);
        }

        // ---- MMA(t): this warp's 2 ksteps x 4 independent acc quads ----
        #pragma unroll
        for (int ks2 = 0; ks2 < 2; ks2++) {
            uint32_t ks = (uint32_t)(kg * 2 + ks2);
            uint32_t ah[4], b0r[4], b1r[4];
            ldm4(ah, bufA + swz(aRowOff + 32u * ks));
            ldm4(b0r, bufB + swz(bBase + 32u * ks));
            ldm4(b1r, bufB + swz(bBase + 2048u + 32u * ks));
            mma16816(acc[0], ah, b0r + 0);
            mma16816(acc[1], ah, b0r + 2);
            mma16816(acc[2], ah, b1r + 0);
            mma16816(acc[3], ah, b1r + 2);
        }

        if (t + 1 < NTILE)
            dacc += phase_a(t + 1, smemA, f1v, nm0, f2s + (t + 1) * KT + c4, aRel);
    }

    // ---- softmax denominator (16 threads per row) ----
    dacc += __shfl_xor_sync(0xffffffffu, dacc, 1);
    dacc += __shfl_xor_sync(0xffffffffu, dacc, 2);
    dacc += __shfl_xor_sync(0xffffffffu, dacc, 4);
    dacc += __shfl_xor_sync(0xffffffffu, dacc, 8);
    if ((lane & 15) == 0) di[r] = 1.0f / dacc;
    __syncthreads();   // MMA done everywhere; di visible; A/B bufs reusable

    // ---- K-group merge via smem scratch (reuses dead A/B buffers) ----
    float* scr = reinterpret_cast<float*>(smemA);   // [16][132] floats
    int rA = lane >> 2;                 // 0..7
    int colb = wc * 32 + 2 * (lane & 3);
    if (kg == 1) {
        #pragma unroll
        for (int nb = 0; nb < 4; nb++) {
            int c = colb + nb * 8;
            *reinterpret_cast<float2*>(&scr[rA * 132 + c]) =
                make_float2(acc[nb][0], acc[nb][1]);
            *reinterpret_cast<float2*>(&scr[(rA + 8) * 132 + c]) =
                make_float2(acc[nb][2], acc[nb][3]);
        }
    }
    __syncthreads();
    if (kg == 0) {
        float d0 = di[rA];
        float d1 = di[rA + 8];
        float* orow0 = out + ((size_t)(b * NN + row0 + rA)) * NF + colb;
        float* orow1 = orow0 + 8 * NF;
        #pragma unroll
        for (int nb = 0; nb < 4; nb++) {
            int c = colb + nb * 8;
            float2 s0 = *reinterpret_cast<float2*>(&scr[rA * 132 + c]);
            float2 s1 = *reinterpret_cast<float2*>(&scr[(rA + 8) * 132 + c]);
            *reinterpret_cast<float2*>(orow0 + nb * 8) =
                make_float2((acc[nb][0] + s0.x) * d0, (acc[nb][1] + s0.y) * d0);
            *reinterpret_cast<float2*>(orow1 + nb * 8) =
                make_float2((acc[nb][2] + s1.x) * d1, (acc[nb][3] + s1.y) * d1);
        }
    }
}

// ---------------------------------------------------------------------------
extern "C" void kernel_launch(void* const* d_in, const int* in_sizes, int n_in,
                              void* d_out, int out_size) {
    const float* h   = (const float*)d_in[0];
    const int*   adj = (const int*)d_in[1];
    const float* W   = (const float*)d_in[2];
    const float* a   = (const float*)d_in[3];
    float* out = (float*)d_out;

    cudaFuncSetAttribute(k_gemm1t, cudaFuncAttributeMaxDynamicSharedMemorySize, G1_SMEM);
    cudaFuncSetAttribute(k_attn,   cudaFuncAttributeMaxDynamicSharedMemorySize, SMEM_TOT);

    k_gemm1t<<<(NB * NN) / 64, 256, G1_SMEM>>>(h, W, a);
    k_attn<<<dim3(NN / RT, NB), 256, SMEM_TOT>>>(adj, out);
}

// round 17
// speedup vs baseline: 1.0639x; 1.0639x over previous
#include <cuda_runtime.h>
#include <cuda_fp16.h>
#include <cstdint>

#define NB 4
#define NN 2048
#define NF 128
#define RT 32        // rows per attention block (M)
#define KT 64        // j per K tile
#define NTILE (NN / KT)
#define SHIFT 4.0f

// ---- scratch (no cudaMalloc allowed) ----
__device__ __half g_WhT_h[NB * NF * NN];   // [b][o][n] fp16
__device__ float  g_f1[NB * NN];
__device__ float  g_f2[NB * NN];

// ---------------------------------------------------------------------------
__device__ __forceinline__ uint32_t smem_u32(const void* p) {
    uint32_t a;
    asm("{ .reg .u64 t; cvta.to.shared.u64 t, %1; cvt.u32.u64 %0, t; }" : "=r"(a) : "l"(p));
    return a;
}
__device__ __forceinline__ uint32_t swz(uint32_t x) { return x ^ ((x >> 3) & 0x70); }

__device__ __forceinline__ uint32_t pkh(float a, float b) {   // fp16x2: lo<-a, hi<-b
    uint32_t r;
    asm("cvt.rn.f16x2.f32 %0, %1, %2;" : "=r"(r) : "f"(b), "f"(a));
    return r;
}
__device__ __forceinline__ void ldm4(uint32_t* r, uint32_t addr) {
    asm volatile("ldmatrix.sync.aligned.m8n8.x4.shared.b16 {%0,%1,%2,%3}, [%4];"
        : "=r"(r[0]), "=r"(r[1]), "=r"(r[2]), "=r"(r[3]) : "r"(addr));
}
__device__ __forceinline__ void mma16816(float* d, const uint32_t* a, const uint32_t* b) {
    asm volatile("mma.sync.aligned.m16n8k16.row.col.f32.f16.f16.f32 "
        "{%0,%1,%2,%3}, {%4,%5,%6,%7}, {%8,%9}, {%0,%1,%2,%3};"
        : "+f"(d[0]), "+f"(d[1]), "+f"(d[2]), "+f"(d[3])
        : "r"(a[0]), "r"(a[1]), "r"(a[2]), "r"(a[3]), "r"(b[0]), "r"(b[1]));
}
#define CPA(dst, src) asm volatile("cp.async.cg.shared.global [%0], [%1], 16;" :: "r"(dst), "l"(src) : "memory")
#define CPC()   asm volatile("cp.async.commit_group;" ::: "memory")
#define CPW(n)  asm volatile("cp.async.wait_group %0;" :: "n"(n) : "memory")

// ---------------------------------------------------------------------------
// Kernel 1 (tensorized): Wh = h@W via 3-term split-fp16 mma.sync.
// ---------------------------------------------------------------------------
#define GA_OFF  0u            // A hi: 2 subs x 8KB; A lo at +16384
#define GB_OFF  32768u        // B hi: 2 subs x 16KB; B lo at +32768 (ends 98304)
#define WF_OFF  98304u        // Wf f32 [128][132] = 67584 (ends 165888)
#define SU_OFF  165888u       // su16 half [128][72] = 18432 (ends 184320)
#define F12_OFF 184320u       // 128 floats (f1 | f2)
#define G1_SMEM (184320 + 512)

__global__ void __launch_bounds__(256, 1)
k_gemm1t(const float* __restrict__ h,
         const float* __restrict__ W,
         const float* __restrict__ a) {
    extern __shared__ char smemA[];
    uint32_t sb = smem_u32(smemA);
    int tid = threadIdx.x;
    int wid = tid >> 5;
    int lane = tid & 31;
    int m0 = blockIdx.x * 64;
    int bb = m0 >> 11;
    int ml = m0 & 2047;

    float* f12 = reinterpret_cast<float*>(smemA + F12_OFF);
    float* Wf  = reinterpret_cast<float*>(smemA + WF_OFF);
    __half* su16 = reinterpret_cast<__half*>(smemA + SU_OFF);

    if (tid < 128) f12[tid] = 0.0f;

    // ---- stage W f32 into smem [128 k][132 pad] (coalesced) ----
    {
        #pragma unroll
        for (int i = 0; i < 16; i++) {
            int w = tid + i * 256;
            int k = w >> 5, c4 = w & 31;
            float4 v = reinterpret_cast<const float4*>(W)[(size_t)k * 32 + c4];
            *reinterpret_cast<float4*>(&Wf[k * 132 + c4 * 4]) = v;
        }
    }

    // ---- convert h rows -> A hi/lo fp16 smem ----
    {
        int r = tid >> 2;
        int cseg = (tid & 3) * 32;
        uint32_t sub = (uint32_t)(cseg >> 6);
        const float4* hp = reinterpret_cast<const float4*>(
            h + (size_t)(m0 + r) * NF + cseg);
        #pragma unroll
        for (int g = 0; g < 4; g++) {
            float4 v0 = hp[g * 2];
            float4 v1 = hp[g * 2 + 1];
            uint32_t h0 = pkh(v0.x, v0.y), h1 = pkh(v0.z, v0.w);
            uint32_t h2 = pkh(v1.x, v1.y), h3 = pkh(v1.z, v1.w);
            float2 f0 = __half22float2(*reinterpret_cast<__half2*>(&h0));
            float2 f1p = __half22float2(*reinterpret_cast<__half2*>(&h1));
            float2 f2p = __half22float2(*reinterpret_cast<__half2*>(&h2));
            float2 f3 = __half22float2(*reinterpret_cast<__half2*>(&h3));
            uint32_t l0 = pkh(v0.x - f0.x, v0.y - f0.y);
            uint32_t l1 = pkh(v0.z - f1p.x, v0.w - f1p.y);
            uint32_t l2 = pkh(v1.x - f2p.x, v1.y - f2p.y);
            uint32_t l3 = pkh(v1.z - f3.x, v1.w - f3.y);
            uint32_t off = sub * 8192u
                         + swz((uint32_t)(r * 128 + ((cseg & 63) + g * 8) * 2));
            *reinterpret_cast<uint4*>(smemA + GA_OFF + off) = make_uint4(h0, h1, h2, h3);
            *reinterpret_cast<uint4*>(smemA + GA_OFF + 16384u + off) = make_uint4(l0, l1, l2, l3);
        }
    }
    __syncthreads();

    // ---- build B (W^T) hi/lo fp16 smem from Wf ----
    {
        int o = tid >> 1;
        int kh = (tid & 1) * 64;
        uint32_t sub = (uint32_t)(tid & 1);
        #pragma unroll
        for (int g = 0; g < 8; g++) {
            int k0 = kh + g * 8;
            float w0 = Wf[(k0 + 0) * 132 + o], w1 = Wf[(k0 + 1) * 132 + o];
            float w2 = Wf[(k0 + 2) * 132 + o], w3 = Wf[(k0 + 3) * 132 + o];
            float w4 = Wf[(k0 + 4) * 132 + o], w5 = Wf[(k0 + 5) * 132 + o];
            float w6 = Wf[(k0 + 6) * 132 + o], w7 = Wf[(k0 + 7) * 132 + o];
            uint32_t h0 = pkh(w0, w1), h1 = pkh(w2, w3);
            uint32_t h2 = pkh(w4, w5), h3 = pkh(w6, w7);
            float2 f0 = __half22float2(*reinterpret_cast<__half2*>(&h0));
            float2 f1p = __half22float2(*reinterpret_cast<__half2*>(&h1));
            float2 f2p = __half22float2(*reinterpret_cast<__half2*>(&h2));
            float2 f3 = __half22float2(*reinterpret_cast<__half2*>(&h3));
            uint32_t l0 = pkh(w0 - f0.x, w1 - f0.y);
            uint32_t l1 = pkh(w2 - f1p.x, w3 - f1p.y);
            uint32_t l2 = pkh(w4 - f2p.x, w5 - f2p.y);
            uint32_t l3 = pkh(w6 - f3.x, w7 - f3.y);
            uint32_t off = sub * 16384u + swz((uint32_t)(o * 128 + g * 16));
            *reinterpret_cast<uint4*>(smemA + GB_OFF + off) = make_uint4(h0, h1, h2, h3);
            *reinterpret_cast<uint4*>(smemA + GB_OFF + 32768u + off) = make_uint4(l0, l1, l2, l3);
        }
    }
    __syncthreads();

    // ---- MMA: warp (wm, wo); 8 ksteps; acc[8][4] ----
    int wm = wid & 3, wo = wid >> 2;
    uint32_t aRowOff = (uint32_t)((wm * 16 + (lane & 7) + ((lane >> 3) & 1) * 8) * 128
                                  + ((lane >> 4) & 1) * 16);
    uint32_t bOff[4];
    #pragma unroll
    for (int nc = 0; nc < 4; nc++) {
        int bRow = wo * 64 + nc * 16 + ((lane >> 4) & 1) * 8 + (lane & 7);
        bOff[nc] = (uint32_t)(bRow * 128) + (uint32_t)(((lane >> 3) & 1) * 16);
    }

    float acc[8][4] = {};
    #pragma unroll
    for (int ks = 0; ks < 8; ks++) {
        uint32_t sub = (uint32_t)(ks >> 2);
        uint32_t ko = 32u * (uint32_t)(ks & 3);
        uint32_t ah[4], al[4], bh[16], bl[16];
        uint32_t aAddr = sb + GA_OFF + sub * 8192u + swz(aRowOff + ko);
        ldm4(ah, aAddr);
        ldm4(al, aAddr + 16384u);
        #pragma unroll
        for (int nc = 0; nc < 4; nc++) {
            uint32_t bAddr = sb + GB_OFF + sub * 16384u + swz(bOff[nc] + ko);
            ldm4(bh + nc * 4, bAddr);
            ldm4(bl + nc * 4, bAddr + 32768u);
        }
        #pragma unroll
        for (int nf = 0; nf < 8; nf++) mma16816(acc[nf], ah, bh + nf * 2);
        #pragma unroll
        for (int nf = 0; nf < 8; nf++) mma16816(acc[nf], ah, bl + nf * 2);
        #pragma unroll
        for (int nf = 0; nf < 8; nf++) mma16816(acc[nf], al, bh + nf * 2);
    }

    // ---- epilogue: f1/f2 partials + transpose buffer ----
    int r0 = wm * 16 + (lane >> 2);
    int r1 = r0 + 8;
    float f1a = 0.f, f1b = 0.f, f2a = 0.f, f2b = 0.f;
    #pragma unroll
    for (int nf = 0; nf < 8; nf++) {
        int c = wo * 64 + nf * 8 + 2 * (lane & 3);
        float a10 = a[c], a11 = a[c + 1];
        float a20 = a[NF + c], a21 = a[NF + c + 1];
        f1a += acc[nf][0] * a10 + acc[nf][1] * a11;
        f1b += acc[nf][2] * a10 + acc[nf][3] * a11;
        f2a += acc[nf][0] * a20 + acc[nf][1] * a21;
        f2b += acc[nf][2] * a20 + acc[nf][3] * a21;
        su16[c * 72 + r0]       = __float2half(acc[nf][0]);
        su16[(c + 1) * 72 + r0] = __float2half(acc[nf][1]);
        su16[c * 72 + r1]       = __float2half(acc[nf][2]);
        su16[(c + 1) * 72 + r1] = __float2half(acc[nf][3]);
    }
    f1a += __shfl_xor_sync(0xffffffffu, f1a, 1);
    f1a += __shfl_xor_sync(0xffffffffu, f1a, 2);
    f1b += __shfl_xor_sync(0xffffffffu, f1b, 1);
    f1b += __shfl_xor_sync(0xffffffffu, f1b, 2);
    f2a += __shfl_xor_sync(0xffffffffu, f2a, 1);
    f2a += __shfl_xor_sync(0xffffffffu, f2a, 2);
    f2b += __shfl_xor_sync(0xffffffffu, f2b, 1);
    f2b += __shfl_xor_sync(0xffffffffu, f2b, 2);
    if ((lane & 3) == 0) {
        atomicAdd(&f12[r0], f1a);
        atomicAdd(&f12[r1], f1b);
        atomicAdd(&f12[64 + r0], f2a);
        atomicAdd(&f12[64 + r1], f2b);
    }
    __syncthreads();

    // ---- global stores ----
    if (tid < 64) g_f1[bb * NN + ml + tid] = f12[tid];
    else if (tid < 128) g_f2[bb * NN + ml + tid - 64] = f12[tid];
    {
        int o = tid >> 1, half = tid & 1;
        const uint4* src = reinterpret_cast<const uint4*>(su16 + o * 72 + half * 32);
        uint4* dst = reinterpret_cast<uint4*>(
            g_WhT_h + (size_t)(bb * 128 + o) * NN + ml + half * 32);
        dst[0] = src[0]; dst[1] = src[1]; dst[2] = src[2]; dst[3] = src[3];
    }
}

// ---------------------------------------------------------------------------
// Kernel 2: fused attention (R15 geometry), hoisted swizzles + f2 prefetch.
// RT=32, 512 threads, 2 CTAs/SM; 16 warps = 2 K-groups x 4 wc; tile 16x32.
// ---------------------------------------------------------------------------
#define AS_OFF  0u            // 2 bufs x 4KB (fp16 P tile 32x64)
#define BT_OFF  8192u         // 2 bufs x 16KB
#define F2_OFF  40960u        // 2048 floats
#define DI_OFF  49152u        // 32 floats
#define SMEM_TOT (49152 + 256)

// phase A for tile tt: adj + f2 already in registers; P into bufA[tt&1]
__device__ __forceinline__ float phase_a(int tt, char* smemA, float f1v, int4 m0,
                                         float4 fa, uint32_t aRel) {
    float s0 = f1v + fa.x; s0 = fmaxf(s0, 0.2f * s0);
    float s1 = f1v + fa.y; s1 = fmaxf(s1, 0.2f * s1);
    float s2 = f1v + fa.z; s2 = fmaxf(s2, 0.2f * s2);
    float s3 = f1v + fa.w; s3 = fmaxf(s3, 0.2f * s3);
    float p0 = (m0.x > 0) ? __expf(s0 - SHIFT) : 0.0f;
    float p1 = (m0.y > 0) ? __expf(s1 - SHIFT) : 0.0f;
    float p2 = (m0.z > 0) ? __expf(s2 - SHIFT) : 0.0f;
    float p3 = (m0.w > 0) ? __expf(s3 - SHIFT) : 0.0f;
    uint32_t off = AS_OFF + (uint32_t)(tt & 1) * 4096u + aRel;
    *reinterpret_cast<uint2*>(smemA + off) = make_uint2(pkh(p0, p1), pkh(p2, p3));
    return (p0 + p1) + (p2 + p3);
}

__global__ void __launch_bounds__(512, 2)
k_attn(const int* __restrict__ adj, float* __restrict__ out) {
    extern __shared__ char smemA[];
    uint32_t sb = smem_u32(smemA);
    int tid = threadIdx.x;
    int wid = tid >> 5;
    int lane = tid & 31;
    int b = blockIdx.y;
    int row0 = blockIdx.x * RT;

    float* f2s = reinterpret_cast<float*>(smemA + F2_OFF);
    float* di = reinterpret_cast<float*>(smemA + DI_OFF);

    // ---- preload f2 row (8KB) ----
    {
        const float4* s4 = reinterpret_cast<const float4*>(g_f2 + b * NN);
        reinterpret_cast<float4*>(f2s)[tid] = s4[tid];
    }

    // ---- per-thread phase-A constants ----
    int r = tid >> 4;                 // 0..31
    int c4 = (tid & 15) * 4;          // j offset within tile
    float f1v = g_f1[b * NN + row0 + r];
    uint32_t aRel = swz((uint32_t)(r * 128 + (tid & 15) * 8));
    const int* adjp = adj + (size_t)(row0 + r) * NN + c4;

    // ---- MMA fragment addresses (hoisted swizzles, loop-invariant) ----
    int kg = wid >> 3;
    int wpos = wid & 7;
    int wr = wpos >> 2, wc = wpos & 3;
    uint32_t aRowOff = (uint32_t)((wr * 16 + (lane & 7) + ((lane >> 3) & 1) * 8) * 128
                                  + ((lane >> 4) & 1) * 16);
    int bRow = wc * 32 + ((lane >> 4) & 1) * 8 + (lane & 7);
    uint32_t bBase = (uint32_t)(bRow * 128) + (uint32_t)(((lane >> 3) & 1) * 16);
    uint32_t swzA[2], swzB0[2], swzB1[2];
    #pragma unroll
    for (int ks2 = 0; ks2 < 2; ks2++) {
        uint32_t ks = (uint32_t)(kg * 2 + ks2);
        swzA[ks2]  = swz(aRowOff + 32u * ks);
        swzB0[ks2] = swz(bBase + 32u * ks);
        swzB1[ks2] = swz(bBase + 2048u + 32u * ks);
    }

    // cp.async B mapping (2 x 16B per thread per tile)
    uint32_t cpDst[2];
    const __half* cpSrcBase[2];
    #pragma unroll
    for (int k = 0; k < 2; k++) {
        int s = tid + k * 512;
        int o = s >> 3, seg = s & 7;
        cpDst[k] = swz((uint32_t)(o * 128 + seg * 16));
        cpSrcBase[k] = g_WhT_h + ((size_t)(b * 128 + o) * NN + seg * 8);
    }

    float acc[4][4] = {};
    float dacc = 0.0f;

    // prologue: B(0); f2 visible; phase A(0)
    CPA(sb + BT_OFF + cpDst[0], cpSrcBase[0]);
    CPA(sb + BT_OFF + cpDst[1], cpSrcBase[1]);
    CPC();
    __syncthreads();
    {
        int4 m0 = *reinterpret_cast<const int4*>(adjp);
        float4 fa = *reinterpret_cast<const float4*>(f2s + c4);
        dacc += phase_a(0, smemA, f1v, m0, fa, aRel);
    }

    for (int t = 0; t < NTILE; t++) {
        uint32_t bufB = sb + BT_OFF + (uint32_t)(t & 1) * 16384u;
        uint32_t bufA = sb + AS_OFF + (uint32_t)(t & 1) * 4096u;

        __syncthreads();   // phaseA(t) + MMA(t-1) complete everywhere

        int4 nm0;
        float4 nf2;
        if (t + 1 < NTILE) {
            uint32_t dbase = sb + BT_OFF + (uint32_t)((t + 1) & 1) * 16384u;
            CPA(dbase + cpDst[0], cpSrcBase[0] + (t + 1) * KT);
            CPA(dbase + cpDst[1], cpSrcBase[1] + (t + 1) * KT);
            CPC();
            nm0 = *reinterpret_cast<const int4*>(adjp + (t + 1) * KT);        // hidden under MMA
            nf2 = *reinterpret_cast<const float4*>(f2s + (t + 1) * KT + c4);  // hidden under MMA
            CPW(1);        // B(t) landed
        } else {
            CPW(0);
        }

        // ---- MMA(t): this warp's 2 ksteps x 4 independent acc quads ----
        #pragma unroll
        for (int ks2 = 0; ks2 < 2; ks2++) {
            uint32_t ah[4], b0r[4], b1r[4];
            ldm4(ah, bufA + swzA[ks2]);
            ldm4(b0r, bufB + swzB0[ks2]);
            ldm4(b1r, bufB + swzB1[ks2]);
            mma16816(acc[0], ah, b0r + 0);
            mma16816(acc[1], ah, b0r + 2);
            mma16816(acc[2], ah, b1r + 0);
            mma16816(acc[3], ah, b1r + 2);
        }

        if (t + 1 < NTILE)
            dacc += phase_a(t + 1, smemA, f1v, nm0, nf2, aRel);
    }

    // ---- softmax denominator (16 threads per row) ----
    dacc += __shfl_xor_sync(0xffffffffu, dacc, 1);
    dacc += __shfl_xor_sync(0xffffffffu, dacc, 2);
    dacc += __shfl_xor_sync(0xffffffffu, dacc, 4);
    dacc += __shfl_xor_sync(0xffffffffu, dacc, 8);
    if ((lane & 15) == 0) di[r] = 1.0f / dacc;
    __syncthreads();   // MMA done everywhere; di visible; A/B bufs reusable

    // ---- K-group merge via smem scratch (reuses dead A/B buffers) ----
    float* scr = reinterpret_cast<float*>(smemA);   // [32][132] floats
    int rA = wr * 16 + (lane >> 2);
    int colb = wc * 32 + 2 * (lane & 3);
    if (kg == 1) {
        #pragma unroll
        for (int nb = 0; nb < 4; nb++) {
            int c = colb + nb * 8;
            *reinterpret_cast<float2*>(&scr[rA * 132 + c]) =
                make_float2(acc[nb][0], acc[nb][1]);
            *reinterpret_cast<float2*>(&scr[(rA + 8) * 132 + c]) =
                make_float2(acc[nb][2], acc[nb][3]);
        }
    }
    __syncthreads();
    if (kg == 0) {
        float d0 = di[rA];
        float d1 = di[rA + 8];
        float* orow0 = out + ((size_t)(b * NN + row0 + rA)) * NF + colb;
        float* orow1 = orow0 + 8 * NF;
        #pragma unroll
        for (int nb = 0; nb < 4; nb++) {
            int c = colb + nb * 8;
            float2 s0 = *reinterpret_cast<float2*>(&scr[rA * 132 + c]);
            float2 s1 = *reinterpret_cast<float2*>(&scr[(rA + 8) * 132 + c]);
            *reinterpret_cast<float2*>(orow0 + nb * 8) =
                make_float2((acc[nb][0] + s0.x) * d0, (acc[nb][1] + s0.y) * d0);
            *reinterpret_cast<float2*>(orow1 + nb * 8) =
                make_float2((acc[nb][2] + s1.x) * d1, (acc[nb][3] + s1.y) * d1);
        }
    }
}

// ---------------------------------------------------------------------------
extern "C" void kernel_launch(void* const* d_in, const int* in_sizes, int n_in,
                              void* d_out, int out_size) {
    const float* h   = (const float*)d_in[0];
    const int*   adj = (const int*)d_in[1];
    const float* W   = (const float*)d_in[2];
    const float* a   = (const float*)d_in[3];
    float* out = (float*)d_out;

    cudaFuncSetAttribute(k_gemm1t, cudaFuncAttributeMaxDynamicSharedMemorySize, G1_SMEM);
    cudaFuncSetAttribute(k_attn,   cudaFuncAttributeMaxDynamicSharedMemorySize, SMEM_TOT);

    k_gemm1t<<<(NB * NN) / 64, 256, G1_SMEM>>>(h, W, a);
    k_attn<<<dim3(NN / RT, NB), 512, SMEM_TOT>>>(adj, out);
}